// round 17
// baseline (speedup 1.0000x reference)
#include <cuda_runtime.h>
#include <cuda_fp16.h>
#include <math.h>

#ifndef M_PI
#define M_PI 3.14159265358979323846
#endif

// Problem constants (fixed shapes: (2,1,2048,2048) images, (3,16,128,128) psfs, overlap=64)
#define IMG     2048
#define HS_     512
#define OV2     32
#define PK      128
#define SEGMAX  576
#define NF      768                     // FFT length = 3 * 4^4  (>= 703 support)
#define NH      385                     // Hermitian rows: fy in [0,384]

#define PD(i)   ((i) + ((i) >> 4))      // smem pad: +1 float2 per 16 (all stages conflict-free)
#define CSTRP   815                     // >= PD(767)+1 = 815
#define TWN     341                     // 256 (W_768^n) + 64 (W_256) + 16 (W_64) + 4 (W_16) + 1
#define S3F     0.86602540378443864676f // sqrt(3)/2
#define NTH     256                     // threads per FFT block (4 columns x TPC=64)

// psf-mid offset inside g_mid (seg-mid @0). Q now lives in its own g_q buffer (fp16).
#define PSFMID  ((size_t)32 * NH * SEGMAX)

// ---------------- static scratch ----------------
__device__ __align__(16) float  g_acc[(size_t)2 * 3 * 16 * SEGMAX * SEGMAX];   // 127 MB (fp32)
__device__ float  g_wtab[4 * 2 * SEGMAX];
__device__ float2 g_twm[TWN];
__device__ ushort2 g_posftab[NH];       // .x = PD(posf(fy)), .y = PD(posf((NF-fy)%NF))
__device__ __align__(16) __half2 g_psfF[(size_t)48 * NH * NF];                 // 56.6 MB fp16
__device__ __align__(16) __half2 g_q[(size_t)96 * NH * SEGMAX];                // 85 MB fp16
// seg mid [32][385][576] @0; psf mid [48][385][128] @PSFMID  (fp32)
__device__ __align__(16) float2 g_mid[PSFMID + (size_t)48 * NH * PK];          // 75.7 MB

__device__ __forceinline__ void tile_range(int i, int* a0, int* a1) {
  int lo = i * HS_ - OV2; if (lo < 0) lo = 0;
  int hi = (i + 1) * HS_ + OV2; if (hi > IMG) hi = IMG;
  *a0 = lo; *a1 = hi;
}
__device__ __forceinline__ float2 cmul(float2 a, float2 b) {
  return make_float2(a.x * b.x - a.y * b.y, a.x * b.y + a.y * b.x);
}
__device__ __forceinline__ int drev4_4(int k) {
  return ((k & 3) << 6) | (((k >> 2) & 3) << 4) | (((k >> 4) & 3) << 2) | ((k >> 6) & 3);
}
__device__ __forceinline__ int posf(int f) {
  return (f % 3) * 256 + drev4_4(f / 3);
}

// radix-4 butterflies operating on registers (outputs in place)
__device__ __forceinline__ void dif4(float2& a, float2& b, float2& c, float2& d, float2 w1) {
  float2 t0 = make_float2(a.x + c.x, a.y + c.y);
  float2 t1 = make_float2(a.x - c.x, a.y - c.y);
  float2 t2 = make_float2(b.x + d.x, b.y + d.y);
  float2 t3 = make_float2(b.x - d.x, b.y - d.y);
  float2 w2 = cmul(w1, w1);
  float2 w3 = cmul(w2, w1);
  float2 u1 = make_float2(t1.x + t3.y, t1.y - t3.x);
  float2 u3 = make_float2(t1.x - t3.y, t1.y + t3.x);
  a = make_float2(t0.x + t2.x, t0.y + t2.y);
  b = cmul(u1, w1);
  c = cmul(make_float2(t0.x - t2.x, t0.y - t2.y), w2);
  d = cmul(u3, w3);
}
__device__ __forceinline__ void dif4_nw(float2& a, float2& b, float2& c, float2& d) {
  float2 t0 = make_float2(a.x + c.x, a.y + c.y);
  float2 t1 = make_float2(a.x - c.x, a.y - c.y);
  float2 t2 = make_float2(b.x + d.x, b.y + d.y);
  float2 t3 = make_float2(b.x - d.x, b.y - d.y);
  a = make_float2(t0.x + t2.x, t0.y + t2.y);
  b = make_float2(t1.x + t3.y, t1.y - t3.x);
  c = make_float2(t0.x - t2.x, t0.y - t2.y);
  d = make_float2(t1.x - t3.y, t1.y + t3.x);
}
// DIT butterfly; w1 is ALREADY conjugated
__device__ __forceinline__ void dit4(float2& a, float2& b, float2& c, float2& d, float2 w1) {
  float2 w2 = cmul(w1, w1);
  float2 w3 = cmul(w2, w1);
  float2 bb = cmul(b, w1), cc = cmul(c, w2), dd = cmul(d, w3);
  float2 t0 = make_float2(a.x + cc.x, a.y + cc.y);
  float2 t1 = make_float2(a.x - cc.x, a.y - cc.y);
  float2 t2 = make_float2(bb.x + dd.x, bb.y + dd.y);
  float2 t3 = make_float2(bb.x - dd.x, bb.y - dd.y);
  a = make_float2(t0.x + t2.x, t0.y + t2.y);
  b = make_float2(t1.x - t3.y, t1.y + t3.x);
  c = make_float2(t0.x - t2.x, t0.y - t2.y);
  d = make_float2(t1.x + t3.y, t1.y - t3.x);
}
__device__ __forceinline__ void dit4_nw(float2& a, float2& b, float2& c, float2& d) {
  float2 t0 = make_float2(a.x + c.x, a.y + c.y);
  float2 t1 = make_float2(a.x - c.x, a.y - c.y);
  float2 t2 = make_float2(b.x + d.x, b.y + d.y);
  float2 t3 = make_float2(b.x - d.x, b.y - d.y);
  a = make_float2(t0.x + t2.x, t0.y + t2.y);
  b = make_float2(t1.x - t3.y, t1.y + t3.x);
  c = make_float2(t0.x - t2.x, t0.y - t2.y);
  d = make_float2(t1.x + t3.y, t1.y - t3.x);
}

// ---------------- init (merged: window + twiddles + scramble table) ----------------
__global__ void init_tabs_kernel() {
  int idx = blockIdx.x * blockDim.x + threadIdx.x;
  if (idx < 4 * 2 * SEGMAX) {
    int p  = idx % SEGMAX;
    int sv = (idx / SEGMAX) & 1;
    int i  = idx / (2 * SEGMAX);
    int a0, a1; tile_range(i, &a0, &a1);
    int S = a1 - a0;
    float val = 0.0f;
    if (p < S) {
      float sigma = sv ? 144.0f : 136.0f;
      float v = -0.5f * (float)S + (float)p * ((float)S / (float)(S - 1));
      val = expf(-0.5f * v * v / (sigma * sigma));
    }
    g_wtab[idx] = val;
  }
  int jt = idx - 4 * 2 * SEGMAX;
  if (jt >= 0 && jt < TWN) {
    double ang;
    if (jt < 256) {
      ang = -2.0 * M_PI * (double)jt / (double)NF;           // W_768^n
    } else {
      int j = jt - 256;
      int m, denom;
      if      (j < 64) { m = j;      denom = 256; }
      else if (j < 80) { m = j - 64; denom = 64;  }
      else if (j < 84) { m = j - 80; denom = 16;  }
      else             { m = 0;      denom = 4;   }
      ang = -2.0 * M_PI * (double)m / (double)denom;
    }
    double sn, cs; sincos(ang, &sn, &cs);
    g_twm[jt] = make_float2((float)cs, (float)sn);
  }
  int pt = idx - (4 * 2 * SEGMAX + TWN);
  if (pt >= 0 && pt < NH) {
    int px = PD(posf(pt));
    int py = PD(posf((NF - pt) % NF));
    g_posftab[pt] = make_ushort2((unsigned short)px, (unsigned short)py);
  }
}

// ---------------- mixed-radix 768-pt FFT (3 * 4^4), register radix-16 stages ------------
template<bool INV>
__device__ __forceinline__ void fft768_run(float2* cols, const float2* tws, int tid) {
  const int TPC = 64;
  float2* col = cols + (tid / TPC) * CSTRP;
  int tc = tid % TPC;
  const float2* tw3 = tws;         // 256: W_768^n
  const float2* tw4 = tws + 256;   // 64 (W_256) + 16 (W_64) + 4 (W_16) + 1
  bool active = (tc < 48);
  int chunk = tc >> 4;
  int mm = tc & 15;
  float2 x[16];
  if (!INV) {
    __syncthreads();
#pragma unroll
    for (int k = 0; k < 4; ++k) {
      int n = tc + 64 * k;
      float2 a = col[PD(n)], b = col[PD(n + 256)], c = col[PD(n + 512)];
      float2 u = make_float2(b.x + c.x, b.y + c.y);
      float2 v = make_float2(b.x - c.x, b.y - c.y);
      float2 t = make_float2(a.x - 0.5f * u.x, a.y - 0.5f * u.y);
      float2 y1 = make_float2(t.x + S3F * v.y, t.y - S3F * v.x);
      float2 y2 = make_float2(t.x - S3F * v.y, t.y + S3F * v.x);
      float2 w1 = tw3[n];
      float2 w2 = cmul(w1, w1);
      col[PD(n)]       = make_float2(a.x + u.x, a.y + u.y);
      col[PD(n + 256)] = cmul(y1, w1);
      col[PD(n + 512)] = cmul(y2, w2);
    }
    __syncthreads();
    if (active) {
      int base = chunk * 256 + mm;
#pragma unroll
      for (int j = 0; j < 16; ++j) x[j] = col[PD(base + 16 * j)];
#pragma unroll
      for (int j0 = 0; j0 < 4; ++j0)
        dif4(x[j0], x[j0 + 4], x[j0 + 8], x[j0 + 12], tw4[mm + 16 * j0]);
      float2 wB = tw4[64 + mm];
#pragma unroll
      for (int a = 0; a < 4; ++a)
        dif4(x[4 * a], x[4 * a + 1], x[4 * a + 2], x[4 * a + 3], wB);
#pragma unroll
      for (int j = 0; j < 16; ++j) col[PD(base + 16 * j)] = x[j];
    }
    __syncthreads();
    if (active) {
      int base = chunk * 256 + 16 * mm;
#pragma unroll
      for (int k = 0; k < 16; ++k) x[k] = col[PD(base + k)];
#pragma unroll
      for (int k0 = 0; k0 < 4; ++k0)
        dif4(x[k0], x[k0 + 4], x[k0 + 8], x[k0 + 12], tw4[80 + k0]);
#pragma unroll
      for (int a = 0; a < 4; ++a)
        dif4_nw(x[4 * a], x[4 * a + 1], x[4 * a + 2], x[4 * a + 3]);
#pragma unroll
      for (int k = 0; k < 16; ++k) col[PD(base + k)] = x[k];
    }
  } else {
    __syncthreads();
    if (active) {
      int base = chunk * 256 + 16 * mm;
#pragma unroll
      for (int k = 0; k < 16; ++k) x[k] = col[PD(base + k)];
#pragma unroll
      for (int a = 0; a < 4; ++a)
        dit4_nw(x[4 * a], x[4 * a + 1], x[4 * a + 2], x[4 * a + 3]);
#pragma unroll
      for (int k0 = 0; k0 < 4; ++k0) {
        float2 w = tw4[80 + k0]; w.y = -w.y;
        dit4(x[k0], x[k0 + 4], x[k0 + 8], x[k0 + 12], w);
      }
#pragma unroll
      for (int k = 0; k < 16; ++k) col[PD(base + k)] = x[k];
    }
    __syncthreads();
    if (active) {
      int base = chunk * 256 + mm;
#pragma unroll
      for (int j = 0; j < 16; ++j) x[j] = col[PD(base + 16 * j)];
      float2 wB = tw4[64 + mm]; wB.y = -wB.y;
#pragma unroll
      for (int a = 0; a < 4; ++a)
        dit4(x[4 * a], x[4 * a + 1], x[4 * a + 2], x[4 * a + 3], wB);
#pragma unroll
      for (int j0 = 0; j0 < 4; ++j0) {
        float2 w = tw4[mm + 16 * j0]; w.y = -w.y;
        dit4(x[j0], x[j0 + 4], x[j0 + 8], x[j0 + 12], w);
      }
#pragma unroll
      for (int j = 0; j < 16; ++j) col[PD(base + 16 * j)] = x[j];
    }
    __syncthreads();
#pragma unroll
    for (int k = 0; k < 4; ++k) {
      int n = tc + 64 * k;
      float2 w1 = tw3[n]; w1.y = -w1.y;
      float2 w2 = cmul(w1, w1);
      float2 z0 = col[PD(n)];
      float2 z1 = cmul(col[PD(n + 256)], w1);
      float2 z2 = cmul(col[PD(n + 512)], w2);
      float2 u = make_float2(z1.x + z2.x, z1.y + z2.y);
      float2 v = make_float2(z1.x - z2.x, z1.y - z2.y);
      float2 t = make_float2(z0.x - 0.5f * u.x, z0.y - 0.5f * u.y);
      col[PD(n)]       = make_float2(z0.x + u.x, z0.y + u.y);
      col[PD(n + 256)] = make_float2(t.x - S3F * v.y, t.y + S3F * v.x);
      col[PD(n + 512)] = make_float2(t.x + S3F * v.y, t.y - S3F * v.x);
    }
  }
  __syncthreads();
}

#define SM4_BYTES  ((TWN + 4 * CSTRP) * sizeof(float2))             // ~28.9 KB
#define SMFU_BYTES ((TWN + 4 * CSTRP + 4 * NF) * sizeof(float2))    // ~53.4 KB (fused)

__device__ __forceinline__ void load_tws(float2* tws, int tid) {
  for (int i = tid; i < TWN; i += NTH) tws[i] = g_twm[i];
}

// ---------------- merged forward y pass: seg (blocks 0..2303) + psf (2304..3071) -------
__global__ __launch_bounds__(NTH, 5) void fwd_y(const float* __restrict__ Timg,
                                                const float* __restrict__ psfs) {
  int bid = blockIdx.x;
  extern __shared__ float2 sm[];
  float2* tws = sm; float2* cols = sm + TWN;
  int tid = threadIdx.x;
  load_tws(tws, tid);
  bool isSeg = (bid < 2304);
  int a = 0, g = 0, ap = 0;
  if (isSeg) { a = bid / 72; g = bid - a * 72; }
  else       { int pb = bid - 2304; ap = pb >> 4; g = pb & 15; }

  if (isSeg) {
    int b = a >> 4, t = a & 15, ti = t >> 2, tj = t & 3;
    int h0, h1, w0, w1; tile_range(ti, &h0, &h1); tile_range(tj, &w0, &w1);
    int Hsz = h1 - h0, Wsz = w1 - w0;
    const float* Tb = Timg + (size_t)b * IMG * IMG;
#pragma unroll
    for (int c = 0; c < 4; ++c) {
      int C0 = g * 8 + 2 * c;
      const float* p0 = Tb + (size_t)(w0 + C0) * IMG;
      const float* p1 = p0 + IMG;
      bool ok0 = (C0 < Wsz), ok1 = (C0 + 1 < Wsz);
      float2* dst = cols + c * CSTRP;
#pragma unroll
      for (int R = tid; R < NF; R += NTH) {
        float vr = 0.0f, vi = 0.0f;
        if (R < Hsz) {
          int base = IMG - 1 - (h0 + R);
          if (ok0) vr = p0[base];
          if (ok1) vi = p1[base];
        }
        dst[PD(R)] = make_float2(vr, vi);
      }
    }
  } else {
    int l = ap / 16, t = ap - l * 16, ti = t >> 2, tj = t & 3;
    int hd = tj * 4 + ti;
    const float* Pb = psfs + ((size_t)l * 16 + hd) * PK * PK;
#pragma unroll
    for (int c = 0; c < 4; ++c) {
      int q0 = g * 8 + 2 * c;
      const float* s0 = Pb + (size_t)q0 * PK;
      const float* s1 = s0 + PK;
      float2* dst = cols + c * CSTRP;
#pragma unroll
      for (int p = tid; p < NF; p += NTH) {
        float vr = 0.0f, vi = 0.0f;
        if (p < PK) {
          vr = s0[PK - 1 - p];
          vi = s1[PK - 1 - p];
        }
        dst[PD(p)] = make_float2(vr, vi);
      }
    }
  }

  fft768_run<false>(cols, tws, tid);

  if (isSeg) {
    float2* outp = g_mid + (size_t)a * NH * SEGMAX;
    for (int idx = tid; idx < NH * 4; idx += NTH) {
      int c = idx & 3, fy = idx >> 2;
      ushort2 pp = g_posftab[fy];
      const float2* colc = cols + c * CSTRP;
      float2 z1 = colc[pp.x];
      float2 z2 = colc[pp.y];
      z2.y = -z2.y;
      float2 c0 = make_float2(0.5f * (z1.x + z2.x), 0.5f * (z1.y + z2.y));
      float2 c1 = make_float2(0.5f * (z1.y - z2.y), -0.5f * (z1.x - z2.x));
      float4* o4 = (float4*)(outp + (size_t)fy * SEGMAX + g * 8 + 2 * c);
      *o4 = make_float4(c0.x, c0.y, c1.x, c1.y);
    }
  } else {
    float2* outp = g_mid + PSFMID + (size_t)ap * NH * PK;
    for (int idx = tid; idx < NH * 4; idx += NTH) {
      int c = idx & 3, fy = idx >> 2;
      ushort2 pp = g_posftab[fy];
      const float2* colc = cols + c * CSTRP;
      float2 z1 = colc[pp.x];
      float2 z2 = colc[pp.y];
      z2.y = -z2.y;
      float2 c0 = make_float2(0.5f * (z1.x + z2.x), 0.5f * (z1.y + z2.y));
      float2 c1 = make_float2(0.5f * (z1.y - z2.y), -0.5f * (z1.x - z2.x));
      float4* o4 = (float4*)(outp + (size_t)fy * PK + g * 8 + 2 * c);
      *o4 = make_float4(c0.x, c0.y, c1.x, c1.y);
    }
  }
}

// ---------------- psf pass 2: forward FFT along q, 4 rows/block; fp16 store ----------
// grid (97, 48)
__global__ __launch_bounds__(NTH, 5) void psf_fx() {
  int fy0 = blockIdx.x * 4, ap = blockIdx.y;
  extern __shared__ float2 sm[];
  float2* tws = sm; float2* cols = sm + TWN;
  int tid = threadIdx.x;
  load_tws(tws, tid);
  const float2* mid = g_mid + PSFMID + (size_t)ap * NH * PK;
#pragma unroll
  for (int row = 0; row < 4; ++row) {
    int fy = fy0 + row; if (fy > NH - 1) fy = NH - 1;
    const float2* src = mid + (size_t)fy * PK;
    float2* dst = cols + row * CSTRP;
#pragma unroll
    for (int C = tid; C < NF; C += NTH)
      dst[PD(C)] = (C < PK) ? src[C] : make_float2(0.0f, 0.0f);
  }
  fft768_run<false>(cols, tws, tid);
#pragma unroll
  for (int row = 0; row < 4; ++row) {
    int fy = fy0 + row;
    if (fy < NH) {
      __half2* dst = g_psfF + ((size_t)ap * NH + fy) * NF;
      const float2* src = cols + row * CSTRP;
#pragma unroll
      for (int fx = tid; fx < NF; fx += NTH)
        dst[fx] = __float22half2_rn(src[PD(fx)]);
    }
  }
}

// ---------------- FUSED: seg forward x-FFT + product + 3x inverse x-IFFT --------------
// grid (97, 32). Q stored fp16 with BOTH 1/NF factors folded in (max |Q| ~ 4e3 << 65504).
__global__ __launch_bounds__(NTH, 4) void segconv_x() {
  int fy0 = blockIdx.x * 4, a = blockIdx.y;
  extern __shared__ float2 sm[];
  float2* tws = sm; float2* cols = sm + TWN; float2* spec = sm + TWN + 4 * CSTRP;
  int tid = threadIdx.x;
  load_tws(tws, tid);
  const float2* mid = g_mid + (size_t)a * NH * SEGMAX;
#pragma unroll
  for (int row = 0; row < 4; ++row) {
    int fy = fy0 + row; if (fy > NH - 1) fy = NH - 1;
    const float2* src = mid + (size_t)fy * SEGMAX;
    float2* dst = cols + row * CSTRP;
#pragma unroll
    for (int C = tid; C < NF; C += NTH)
      dst[PD(C)] = (C < SEGMAX) ? src[C] : make_float2(0.0f, 0.0f);
  }
  fft768_run<false>(cols, tws, tid);
#pragma unroll
  for (int row = 0; row < 4; ++row) {
    float2* sp = spec + row * NF;
    const float2* src = cols + row * CSTRP;
#pragma unroll
    for (int p = tid; p < NF; p += NTH) sp[p] = src[PD(p)];
  }
  __syncthreads();
  const float sc2 = (1.0f / (float)NF) * (1.0f / (float)NF);
#pragma unroll 1
  for (int l = 0; l < 3; ++l) {
    int al = l * 16 + (a & 15);
    const __half2* Fb = g_psfF + (size_t)al * NH * NF;
#pragma unroll
    for (int row = 0; row < 4; ++row) {
      int fy = fy0 + row; if (fy > NH - 1) fy = NH - 1;
      const __half2* Frow = Fb + (size_t)fy * NF;
      const float2* sp = spec + row * NF;
      float2* dst = cols + row * CSTRP;
#pragma unroll
      for (int p = tid; p < NF; p += NTH) {
        float2 F = __half22float2(Frow[p]);
        dst[PD(p)] = cmul(sp[p], F);
      }
    }
    fft768_run<true>(cols, tws, tid);
    __half2* Q = g_q + (size_t)(l * 32 + a) * NH * SEGMAX;
#pragma unroll
    for (int row = 0; row < 4; ++row) {
      int fy = fy0 + row;
      if (fy < NH) {
        __half2* q = Q + (size_t)fy * SEGMAX;
        const float2* src = cols + row * CSTRP;
#pragma unroll
        for (int x = tid; x < SEGMAX; x += NTH) {
          float2 v = src[PD(64 + x)];
          q[x] = __float22half2_rn(make_float2(v.x * sc2, v.y * sc2));
        }
      }
    }
    __syncthreads();   // protect cols before next l overwrites
  }
}

// ---------------- inverse pass B: C2R IFFT along y (two columns per FFT) -------------
// grid (72, 32, 3). Q is fp16, pre-scaled -> unscaled IFFT here. Window + store g_acc.
__global__ __launch_bounds__(NTH, 5) void conv_y() {
  int g = blockIdx.x, a = blockIdx.y, l = blockIdx.z;
  int b = a >> 4, t = a & 15, ti = t >> 2, tj = t & 3;
  int h0, h1, w0, w1; tile_range(ti, &h0, &h1); tile_range(tj, &w0, &w1);
  int Hsz = h1 - h0, Wsz = w1 - w0;
  extern __shared__ float2 sm[];
  float2* tws = sm; float2* cols = sm + TWN;
  int tid = threadIdx.x;
  load_tws(tws, tid);
  const __half2* Q = g_q + (size_t)(l * 32 + a) * NH * SEGMAX;
  for (int idx = tid; idx < NH * 4; idx += NTH) {
    int c = idx & 3, fy = idx >> 2;
    ushort2 pp = g_posftab[fy];
    uint2 u = *(const uint2*)(Q + (size_t)fy * SEGMAX + g * 8 + 2 * c);
    float2 q0 = __half22float2(*(__half2*)&u.x);
    float2 q1 = __half22float2(*(__half2*)&u.y);
    float2* colc = cols + c * CSTRP;
    colc[pp.x] = make_float2(q0.x - q1.y, q0.y + q1.x);
    if (fy >= 1 && fy <= NF / 2 - 1)
      colc[pp.y] = make_float2(q0.x + q1.y, q1.x - q0.y);
  }
  fft768_run<true>(cols, tws, tid);
  int sv = (Hsz == 576 && Wsz == 576) ? 1 : 0;
  float* outbase = g_acc + (size_t)((b * 3 + l) * 16 + t) * (SEGMAX * SEGMAX);
  for (int idx = tid; idx < 4 * SEGMAX; idx += NTH) {
    int c = idx & 3, r = idx >> 2;
    int x0 = g * 8 + 2 * c;
    if (r < Hsz && x0 < Wsz) {
      float2 v = cols[c * CSTRP + PD(r + 64)];
      float wy  = g_wtab[(ti * 2 + sv) * SEGMAX + r];
      float wx0 = g_wtab[(tj * 2 + sv) * SEGMAX + x0];
      float wx1 = g_wtab[(tj * 2 + sv) * SEGMAX + x0 + 1];
      float2 o = make_float2(v.x * wy * wx0, v.y * wy * wx1);
      *(float2*)(outbase + (size_t)r * Wsz + x0) = o;
    }
  }
}

// ---------------- overlap-add gather + normalize + rotation via smem transpose -------
__global__ __launch_bounds__(256) void finalize_t(float* __restrict__ outp) {
  int J0 = blockIdx.x * 32, I0 = blockIdx.y * 32;
  int z = blockIdx.z;            // z = b*3 + l
  __shared__ float ssum[32][33];
  __shared__ float swin[32][33];
  int lx = threadIdx.x, ly = threadIdx.y;
  for (int yy = ly; yy < 32; yy += 8) { ssum[yy][lx] = 0.0f; swin[yy][lx] = 0.0f; }
  __syncthreads();
  int ylo = IMG - 1 - (J0 + 31);
#pragma unroll
  for (int i = 0; i < 4; ++i) {
    int h0, h1; tile_range(i, &h0, &h1);
    if (ylo + 31 < h0 || ylo >= h1) continue;
#pragma unroll
    for (int j = 0; j < 4; ++j) {
      int w0, w1; tile_range(j, &w0, &w1);
      if (I0 + 31 < w0 || I0 >= w1) continue;
      int Hsz = h1 - h0, Wsz = w1 - w0;
      int sv = (Hsz == 576 && Wsz == 576) ? 1 : 0;
      const float* base = g_acc + (size_t)(z * 16 + i * 4 + j) * (SEGMAX * SEGMAX);
      int x = I0 + lx;
      bool xok = (x >= w0 && x < w1);
      float wx = xok ? g_wtab[(j * 2 + sv) * SEGMAX + (x - w0)] : 0.0f;
      for (int yy = ly; yy < 32; yy += 8) {
        int y = ylo + yy;
        if (xok && y >= h0 && y < h1) {
          int r = y - h0;
          ssum[yy][lx] += base[(size_t)r * Wsz + (x - w0)];
          swin[yy][lx] += g_wtab[(i * 2 + sv) * SEGMAX + r] * wx;
        }
      }
    }
  }
  __syncthreads();
  for (int ii = ly; ii < 32; ii += 8) {
    int I = I0 + ii;
    int J = J0 + lx;
    int yy = 31 - lx;
    float s = ssum[yy][ii];
    float w = swin[yy][ii];
    float res = s / fmaxf(w, 1e-12f);
    if (!(res == res)) res = 0.0f;
    outp[((size_t)z * IMG + I) * IMG + J] = res;
  }
}

extern "C" void kernel_launch(void* const* d_in, const int* in_sizes, int n_in,
                              void* d_out, int out_size) {
  const float* Timg = (const float*)d_in[0];
  const float* psfs = (const float*)d_in[1];
  (void)in_sizes; (void)n_in;
  float* outp = (float*)d_out;

  cudaFuncSetAttribute(fwd_y,     cudaFuncAttributeMaxDynamicSharedMemorySize, (int)SM4_BYTES);
  cudaFuncSetAttribute(psf_fx,    cudaFuncAttributeMaxDynamicSharedMemorySize, (int)SM4_BYTES);
  cudaFuncSetAttribute(segconv_x, cudaFuncAttributeMaxDynamicSharedMemorySize, (int)SMFU_BYTES);
  cudaFuncSetAttribute(conv_y,    cudaFuncAttributeMaxDynamicSharedMemorySize, (int)SM4_BYTES);

  init_tabs_kernel<<<21, 256>>>();

  fwd_y<<<3072, NTH, SM4_BYTES>>>(Timg, psfs);     // seg_fy (2304) + psf_fy (768)
  psf_fx<<<dim3(97, 48), NTH, SM4_BYTES>>>();
  segconv_x<<<dim3(97, 32), NTH, SMFU_BYTES>>>();
  conv_y<<<dim3(72, 32, 3), NTH, SM4_BYTES>>>();

  finalize_t<<<dim3(64, 64, 6), dim3(32, 8)>>>(outp);
}